// round 7
// baseline (speedup 1.0000x reference)
#include <cuda_runtime.h>
#include <cuda_bf16.h>
#include <stdint.h>
#include <math.h>

// Problem dims (fixed for this problem)
#define TKN 32768        // B*S = 8*4096 tokens
#define DIM 768          // D
#define HID 2048         // H
#define N1  4096         // 2H
#define KI1 192          // DIM/4  (K in int32 units for GEMM1)
#define KI2 512          // HID/4  (K in int32 units for GEMM2)

// ---------------- scratch (device globals; no allocation allowed) ----------------
// __align__(256): int8_t __device__ arrays only guarantee 1-byte alignment and we
// do 16B vector accesses relative to the base.
__device__ __align__(256) double g_acc[2];                 // abs-sum accumulators
__device__ __align__(256) float  g_wdq[2];                 // 1/scale_w per weight
__device__ __align__(256) int8_t g_xq[(size_t)TKN * DIM];  // quantized x_norm
__device__ __align__(256) float  g_xdq[TKN];               // per-token 1/scale_x
__device__ __align__(256) int8_t g_w1q[(size_t)N1 * DIM];  // ternary w_in
__device__ __align__(256) int8_t g_w2q[(size_t)DIM * HID]; // ternary w_out
__device__ __align__(256) float  g_y[(size_t)TKN * HID];   // swiglu output (fp32)
__device__ __align__(256) int8_t g_yq[(size_t)TKN * HID];  // quantized y_norm
__device__ __align__(256) float  g_ydq[TKN];               // per-token 1/scale_y

// ---------------- reductions ----------------
__device__ __forceinline__ float blockAllReduceSum(float v) {
    __shared__ float sm[17];
    int lane = threadIdx.x & 31, wid = threadIdx.x >> 5;
#pragma unroll
    for (int o = 16; o; o >>= 1) v += __shfl_down_sync(0xffffffffu, v, o);
    if (lane == 0) sm[wid] = v;
    __syncthreads();
    if (wid == 0) {
        float t = (lane < (int)(blockDim.x >> 5)) ? sm[lane] : 0.0f;
#pragma unroll
        for (int o = 16; o; o >>= 1) t += __shfl_down_sync(0xffffffffu, t, o);
        if (lane == 0) sm[16] = t;
    }
    __syncthreads();
    float r = sm[16];
    __syncthreads();
    return r;
}

__device__ __forceinline__ float blockAllReduceMax(float v) {
    __shared__ float sm[17];
    int lane = threadIdx.x & 31, wid = threadIdx.x >> 5;
#pragma unroll
    for (int o = 16; o; o >>= 1) v = fmaxf(v, __shfl_down_sync(0xffffffffu, v, o));
    if (lane == 0) sm[wid] = v;
    __syncthreads();
    if (wid == 0) {
        float t = (lane < (int)(blockDim.x >> 5)) ? sm[lane] : 0.0f;
#pragma unroll
        for (int o = 16; o; o >>= 1) t = fmaxf(t, __shfl_down_sync(0xffffffffu, t, o));
        if (lane == 0) sm[16] = t;
    }
    __syncthreads();
    float r = sm[16];
    __syncthreads();
    return r;
}

// ---------------- weight quantization ----------------
__global__ void k_init() { g_acc[0] = 0.0; g_acc[1] = 0.0; }

__global__ void k_abssum(const float* __restrict__ w, int n, int idx) {
    double s = 0.0;
    for (int i = blockIdx.x * blockDim.x + threadIdx.x; i < n; i += gridDim.x * blockDim.x)
        s += (double)fabsf(w[i]);
#pragma unroll
    for (int o = 16; o; o >>= 1) s += __shfl_down_sync(0xffffffffu, s, o);
    __shared__ double sm[8];
    int lane = threadIdx.x & 31, wid = threadIdx.x >> 5;
    if (lane == 0) sm[wid] = s;
    __syncthreads();
    if (wid == 0) {
        s = (lane < (int)(blockDim.x >> 5)) ? sm[lane] : 0.0;
#pragma unroll
        for (int o = 4; o; o >>= 1) s += __shfl_down_sync(0xffffffffu, s, o);
        if (lane == 0) atomicAdd(&g_acc[idx], s);
    }
}

// ternary quant: q = clip(round(w*scale), -1, 1), scale = 1/max(mean|w|, 1e-5)
// FIX: the int8 destination is selected INSIDE device code via idx. Previously
// g_w1q/g_w2q were passed by name from host code — that passes the HOST shadow
// address, not the device array (invalid; caused the zero/poison output).
__global__ void k_wquant(const float* __restrict__ w, int n4, int idx, double inv_n) {
    int8_t* __restrict__ q = (idx == 0) ? g_w1q : g_w2q;
    float mean = (float)(g_acc[idx] * inv_n);
    float scale = 1.0f / fmaxf(mean, 1e-5f);
    int i = blockIdx.x * blockDim.x + threadIdx.x;
    if (i < n4) {
        float4 v = ((const float4*)w)[i];
        char4 c;
        c.x = (char)max(-1, min(1, (int)rintf(v.x * scale)));
        c.y = (char)max(-1, min(1, (int)rintf(v.y * scale)));
        c.z = (char)max(-1, min(1, (int)rintf(v.z * scale)));
        c.w = (char)max(-1, min(1, (int)rintf(v.w * scale)));
        ((char4*)q)[i] = c;
    }
    if (i == 0) g_wdq[idx] = 1.0f / scale;
}

// ---------------- fused rmsnorm + per-token int8 activation quant ----------------
__device__ __forceinline__ void rowquant_body(const float* __restrict__ in,
                                              const float* __restrict__ gain,
                                              int8_t* __restrict__ q,
                                              float* __restrict__ dq) {
    int t = blockIdx.x;
    int tid = threadIdx.x;
    int ld4 = blockDim.x;
    size_t base = (size_t)t * ld4 + tid;
    float4 v = ((const float4*)in)[base];
    float ss = v.x * v.x + v.y * v.y + v.z * v.z + v.w * v.w;
    ss = blockAllReduceSum(ss);
    float mn = ss / (float)(ld4 * 4) + 1e-6f;          // mean(x^2) + EPS_NORM
    float rs = (float)(1.0 / sqrt((double)mn));
    float4 gv = ((const float4*)gain)[tid];
    float4 nv = make_float4((v.x * rs) * gv.x, (v.y * rs) * gv.y,
                            (v.z * rs) * gv.z, (v.w * rs) * gv.w);
    float am = fmaxf(fmaxf(fabsf(nv.x), fabsf(nv.y)), fmaxf(fabsf(nv.z), fabsf(nv.w)));
    am = blockAllReduceMax(am);
    float scale = 127.0f / fmaxf(am, 1e-5f);           // EPS_Q
    char4 c;
    c.x = (char)max(-128, min(127, (int)rintf(nv.x * scale)));
    c.y = (char)max(-128, min(127, (int)rintf(nv.y * scale)));
    c.z = (char)max(-128, min(127, (int)rintf(nv.z * scale)));
    c.w = (char)max(-128, min(127, (int)rintf(nv.w * scale)));
    ((char4*)q)[base] = c;
    if (tid == 0) dq[t] = 1.0f / scale;
}

__global__ void k_quant_x(const float* __restrict__ x, const float* __restrict__ gain) {
    rowquant_body(x, gain, g_xq, g_xdq);   // device-side symbol refs: valid
}
__global__ void k_quant_y(const float* __restrict__ gain) {
    rowquant_body(g_y, gain, g_yq, g_ydq);
}

// ---------------- GEMM1 (int8 dp4a) + fused swiglu ----------------
__global__ void __launch_bounds__(256) k_gemm1() {
    __shared__ int As[16][64];
    __shared__ int Bu[16][64];
    __shared__ int Bg[16][64];
    const int* xi = (const int*)g_xq;
    const int* wi = (const int*)g_w1q;
    int m0 = blockIdx.y << 6;
    int n0 = blockIdx.x << 6;
    int tid = threadIdx.x;
    int tx = tid & 15, ty = tid >> 4;
    int lr = tid >> 2;           // 0..63 : row within tile
    int lc = (tid & 3) << 2;     // 0,4,8,12 : kint offset
    int acc_u[4][4], acc_g[4][4];
#pragma unroll
    for (int i = 0; i < 4; i++)
#pragma unroll
        for (int j = 0; j < 4; j++) { acc_u[i][j] = 0; acc_g[i][j] = 0; }

    for (int k0 = 0; k0 < KI1; k0 += 16) {
        int4 a  = *(const int4*)&xi[(size_t)(m0 + lr) * KI1 + k0 + lc];
        int4 bu = *(const int4*)&wi[(size_t)(n0 + lr) * KI1 + k0 + lc];
        int4 bg = *(const int4*)&wi[(size_t)(HID + n0 + lr) * KI1 + k0 + lc];
        __syncthreads();
        As[lc][lr] = a.x;  As[lc+1][lr] = a.y;  As[lc+2][lr] = a.z;  As[lc+3][lr] = a.w;
        Bu[lc][lr] = bu.x; Bu[lc+1][lr] = bu.y; Bu[lc+2][lr] = bu.z; Bu[lc+3][lr] = bu.w;
        Bg[lc][lr] = bg.x; Bg[lc+1][lr] = bg.y; Bg[lc+2][lr] = bg.z; Bg[lc+3][lr] = bg.w;
        __syncthreads();
#pragma unroll
        for (int kk = 0; kk < 16; kk++) {
            int4 av = *(const int4*)&As[kk][ty << 2];
            int4 bv = *(const int4*)&Bu[kk][tx << 2];
            int4 gv = *(const int4*)&Bg[kk][tx << 2];
            int aa[4] = {av.x, av.y, av.z, av.w};
            int bb[4] = {bv.x, bv.y, bv.z, bv.w};
            int gg[4] = {gv.x, gv.y, gv.z, gv.w};
#pragma unroll
            for (int i = 0; i < 4; i++)
#pragma unroll
                for (int j = 0; j < 4; j++) {
                    acc_u[i][j] = __dp4a(aa[i], bb[j], acc_u[i][j]);
                    acc_g[i][j] = __dp4a(aa[i], gg[j], acc_g[i][j]);
                }
        }
    }
    float wdq = g_wdq[0];
#pragma unroll
    for (int i = 0; i < 4; i++) {
        int m = m0 + (ty << 2) + i;
        float s = g_xdq[m] * wdq;
        float4 o;
        float* op = &o.x;
#pragma unroll
        for (int j = 0; j < 4; j++) {
            float up = (float)acc_u[i][j] * s;
            float gt = (float)acc_g[i][j] * s;
            float sig = 1.0f / (1.0f + expf(-gt));
            op[j] = (gt * sig) * up;   // silu(gate) * up
        }
        *(float4*)&g_y[(size_t)m * HID + n0 + (tx << 2)] = o;
    }
}

// ---------------- GEMM2 (int8 dp4a) ----------------
__global__ void __launch_bounds__(256) k_gemm2(float* __restrict__ out) {
    __shared__ int As[16][64];
    __shared__ int Bs[16][64];
    const int* yi = (const int*)g_yq;
    const int* wi = (const int*)g_w2q;
    int m0 = blockIdx.y << 6;
    int n0 = blockIdx.x << 6;
    int tid = threadIdx.x;
    int tx = tid & 15, ty = tid >> 4;
    int lr = tid >> 2;
    int lc = (tid & 3) << 2;
    int acc[4][4];
#pragma unroll
    for (int i = 0; i < 4; i++)
#pragma unroll
        for (int j = 0; j < 4; j++) acc[i][j] = 0;

    for (int k0 = 0; k0 < KI2; k0 += 16) {
        int4 a = *(const int4*)&yi[(size_t)(m0 + lr) * KI2 + k0 + lc];
        int4 b = *(const int4*)&wi[(size_t)(n0 + lr) * KI2 + k0 + lc];
        __syncthreads();
        As[lc][lr] = a.x; As[lc+1][lr] = a.y; As[lc+2][lr] = a.z; As[lc+3][lr] = a.w;
        Bs[lc][lr] = b.x; Bs[lc+1][lr] = b.y; Bs[lc+2][lr] = b.z; Bs[lc+3][lr] = b.w;
        __syncthreads();
#pragma unroll
        for (int kk = 0; kk < 16; kk++) {
            int4 av = *(const int4*)&As[kk][ty << 2];
            int4 bv = *(const int4*)&Bs[kk][tx << 2];
            int aa[4] = {av.x, av.y, av.z, av.w};
            int bb[4] = {bv.x, bv.y, bv.z, bv.w};
#pragma unroll
            for (int i = 0; i < 4; i++)
#pragma unroll
                for (int j = 0; j < 4; j++)
                    acc[i][j] = __dp4a(aa[i], bb[j], acc[i][j]);
        }
    }
    float wdq = g_wdq[1];
#pragma unroll
    for (int i = 0; i < 4; i++) {
        int m = m0 + (ty << 2) + i;
        float s = g_ydq[m] * wdq;
        float4 o;
        o.x = (float)acc[i][0] * s;
        o.y = (float)acc[i][1] * s;
        o.z = (float)acc[i][2] * s;
        o.w = (float)acc[i][3] * s;
        *(float4*)&out[(size_t)m * DIM + n0 + (tx << 2)] = o;
    }
}

// ---------------- eager init: absorb first-launch driver pool growth ----------------
namespace {
struct EagerInit {
    EagerInit() {
        cudaFree(0);  // establish context
        void* py = nullptr; void* pdq = nullptr;
        cudaGetSymbolAddress(&py, g_y);     // valid device pointers via API
        cudaGetSymbolAddress(&pdq, g_xdq);
        const float* fy = (const float*)py;
        k_init<<<1, 1>>>();
        k_abssum<<<2, 256>>>(fy, 1024, 0);
        k_wquant<<<1, 256>>>(fy, 256, 0, 1.0);
        k_quant_x<<<1, DIM / 4>>>(fy, (const float*)pdq);
        k_quant_y<<<1, HID / 4>>>((const float*)pdq);
        k_gemm1<<<dim3(1, 1), 256>>>();
        k_gemm2<<<dim3(1, 1), 256>>>((float*)py);
        cudaDeviceSynchronize();
        cudaGetLastError();  // clear any residue
    }
};
EagerInit eager_init_;
}  // namespace

// ---------------- launch ----------------
extern "C" void kernel_launch(void* const* d_in, const int* in_sizes, int n_in,
                              void* d_out, int out_size) {
    // Dual-unit size matching (elements OR bytes), rank fallback.
    const float* x = nullptr, *w_in = nullptr, *gin = nullptr,
               *w_out = nullptr, *gout = nullptr;
    for (int i = 0; i < n_in; i++) {
        long long s = in_sizes[i];
        if (s == 25165824LL || s == 100663296LL)      x     = (const float*)d_in[i];
        else if (s == 3145728LL || s == 12582912LL)   w_in  = (const float*)d_in[i];
        else if (s == 1572864LL || s == 6291456LL)    w_out = (const float*)d_in[i];
        else if (s == 768LL     || s == 3072LL)       gin   = (const float*)d_in[i];
        else if (s == 2048LL    || s == 8192LL)       gout  = (const float*)d_in[i];
    }
    if (!x || !w_in || !gin || !w_out || !gout) {
        int idx[16];
        int m = n_in < 16 ? n_in : 16;
        for (int i = 0; i < m; i++) idx[i] = i;
        for (int a = 0; a < m; a++)
            for (int b = a + 1; b < m; b++)
                if ((long long)in_sizes[idx[b]] < (long long)in_sizes[idx[a]]) {
                    int t = idx[a]; idx[a] = idx[b]; idx[b] = t;
                }
        gin   = (const float*)d_in[idx[0]];
        gout  = (const float*)d_in[idx[1]];
        w_out = (const float*)d_in[idx[2]];
        w_in  = (const float*)d_in[idx[3]];
        x     = (const float*)d_in[idx[4]];
    }
    float* out = (float*)d_out;                  // [8,4096,768] float32

    // 1) weight abs-mean reductions
    k_init<<<1, 1>>>();
    k_abssum<<<512, 256>>>(w_in,  N1 * DIM, 0);
    k_abssum<<<512, 256>>>(w_out, DIM * HID, 1);

    // 2) ternary weight quant (destination selected device-side by idx)
    k_wquant<<<(N1 * DIM / 4 + 255) / 256, 256>>>(w_in,  N1 * DIM / 4, 0,
                                                  1.0 / (double)(N1 * DIM));
    k_wquant<<<(DIM * HID / 4 + 255) / 256, 256>>>(w_out, DIM * HID / 4, 1,
                                                   1.0 / (double)(DIM * HID));

    // 3) rmsnorm + act quant of x
    k_quant_x<<<TKN, DIM / 4>>>(x, gin);

    // 4) GEMM1 + swiglu -> y
    k_gemm1<<<dim3(HID / 64, TKN / 64), 256>>>();

    // 5) rmsnorm + act quant of y
    k_quant_y<<<TKN, HID / 4>>>(gout);

    // 6) GEMM2 -> out
    k_gemm2<<<dim3(DIM / 64, TKN / 64), 256>>>(out);
}

// round 8
// speedup vs baseline: 3.4065x; 3.4065x over previous
#include <cuda_runtime.h>
#include <cuda_bf16.h>
#include <stdint.h>
#include <math.h>

// Problem dims (fixed)
#define TKN 32768        // B*S
#define DIM 768
#define HID 2048
#define N1  4096         // 2H

// ---------------- scratch ----------------
__device__ __align__(256) double g_acc[2];
__device__ __align__(256) float  g_wdq[2];
__device__ __align__(256) int8_t g_xq[(size_t)TKN * DIM];
__device__ __align__(256) float  g_xdq[TKN];
__device__ __align__(256) int8_t g_w1q[(size_t)N1 * DIM];
__device__ __align__(256) int8_t g_w2q[(size_t)DIM * HID];
__device__ __align__(256) float  g_y[(size_t)TKN * HID];
__device__ __align__(256) int8_t g_yq[(size_t)TKN * HID];
__device__ __align__(256) float  g_ydq[TKN];

// ---------------- helpers ----------------
__device__ __forceinline__ uint32_t smem_u32(const void* p) {
    return (uint32_t)__cvta_generic_to_shared(p);
}
__device__ __forceinline__ void cp16(uint32_t s, const void* g) {
    asm volatile("cp.async.cg.shared.global [%0], [%1], 16;" :: "r"(s), "l"(g));
}
__device__ __forceinline__ void cp_commit() { asm volatile("cp.async.commit_group;"); }
template <int N> __device__ __forceinline__ void cp_wait() {
    asm volatile("cp.async.wait_group %0;" :: "n"(N));
}
__device__ __forceinline__ void mma_s8(int* c, int a0, int a1, int a2, int a3,
                                       int b0, int b1) {
    asm volatile(
        "mma.sync.aligned.m16n8k32.row.col.s32.s8.s8.s32 "
        "{%0,%1,%2,%3}, {%4,%5,%6,%7}, {%8,%9}, {%0,%1,%2,%3};"
        : "+r"(c[0]), "+r"(c[1]), "+r"(c[2]), "+r"(c[3])
        : "r"(a0), "r"(a1), "r"(a2), "r"(a3), "r"(b0), "r"(b1));
}

// ---------------- reductions ----------------
__device__ __forceinline__ float blockAllReduceSum(float v) {
    __shared__ float sm[17];
    int lane = threadIdx.x & 31, wid = threadIdx.x >> 5;
#pragma unroll
    for (int o = 16; o; o >>= 1) v += __shfl_down_sync(0xffffffffu, v, o);
    if (lane == 0) sm[wid] = v;
    __syncthreads();
    if (wid == 0) {
        float t = (lane < (int)(blockDim.x >> 5)) ? sm[lane] : 0.0f;
#pragma unroll
        for (int o = 16; o; o >>= 1) t += __shfl_down_sync(0xffffffffu, t, o);
        if (lane == 0) sm[16] = t;
    }
    __syncthreads();
    float r = sm[16];
    __syncthreads();
    return r;
}
__device__ __forceinline__ float blockAllReduceMax(float v) {
    __shared__ float sm[17];
    int lane = threadIdx.x & 31, wid = threadIdx.x >> 5;
#pragma unroll
    for (int o = 16; o; o >>= 1) v = fmaxf(v, __shfl_down_sync(0xffffffffu, v, o));
    if (lane == 0) sm[wid] = v;
    __syncthreads();
    if (wid == 0) {
        float t = (lane < (int)(blockDim.x >> 5)) ? sm[lane] : 0.0f;
#pragma unroll
        for (int o = 16; o; o >>= 1) t = fmaxf(t, __shfl_down_sync(0xffffffffu, t, o));
        if (lane == 0) sm[16] = t;
    }
    __syncthreads();
    float r = sm[16];
    __syncthreads();
    return r;
}

// ---------------- weight quantization ----------------
__global__ void k_init() { g_acc[0] = 0.0; g_acc[1] = 0.0; }

__global__ void k_abssum(const float* __restrict__ w, int n, int idx) {
    double s = 0.0;
    for (int i = blockIdx.x * blockDim.x + threadIdx.x; i < n; i += gridDim.x * blockDim.x)
        s += (double)fabsf(w[i]);
#pragma unroll
    for (int o = 16; o; o >>= 1) s += __shfl_down_sync(0xffffffffu, s, o);
    __shared__ double sm[8];
    int lane = threadIdx.x & 31, wid = threadIdx.x >> 5;
    if (lane == 0) sm[wid] = s;
    __syncthreads();
    if (wid == 0) {
        s = (lane < (int)(blockDim.x >> 5)) ? sm[lane] : 0.0;
#pragma unroll
        for (int o = 4; o; o >>= 1) s += __shfl_down_sync(0xffffffffu, s, o);
        if (lane == 0) atomicAdd(&g_acc[idx], s);
    }
}

// destination selected device-side (host must never pass __device__ symbols)
__global__ void k_wquant(const float* __restrict__ w, int n4, int idx, double inv_n) {
    int8_t* __restrict__ q = (idx == 0) ? g_w1q : g_w2q;
    float mean = (float)(g_acc[idx] * inv_n);
    float scale = 1.0f / fmaxf(mean, 1e-5f);
    int i = blockIdx.x * blockDim.x + threadIdx.x;
    if (i < n4) {
        float4 v = ((const float4*)w)[i];
        char4 c;
        c.x = (char)max(-1, min(1, (int)rintf(v.x * scale)));
        c.y = (char)max(-1, min(1, (int)rintf(v.y * scale)));
        c.z = (char)max(-1, min(1, (int)rintf(v.z * scale)));
        c.w = (char)max(-1, min(1, (int)rintf(v.w * scale)));
        ((char4*)q)[i] = c;
    }
    if (i == 0) g_wdq[idx] = 1.0f / scale;
}

// ---------------- fused rmsnorm + per-token int8 activation quant ----------------
__device__ __forceinline__ void rowquant_body(const float* __restrict__ in,
                                              const float* __restrict__ gain,
                                              int8_t* __restrict__ q,
                                              float* __restrict__ dq) {
    int t = blockIdx.x;
    int tid = threadIdx.x;
    int ld4 = blockDim.x;
    size_t base = (size_t)t * ld4 + tid;
    float4 v = ((const float4*)in)[base];
    float ss = v.x * v.x + v.y * v.y + v.z * v.z + v.w * v.w;
    ss = blockAllReduceSum(ss);
    float mn = ss / (float)(ld4 * 4) + 1e-6f;
    float rs = (float)(1.0 / sqrt((double)mn));
    float4 gv = ((const float4*)gain)[tid];
    float4 nv = make_float4((v.x * rs) * gv.x, (v.y * rs) * gv.y,
                            (v.z * rs) * gv.z, (v.w * rs) * gv.w);
    float am = fmaxf(fmaxf(fabsf(nv.x), fabsf(nv.y)), fmaxf(fabsf(nv.z), fabsf(nv.w)));
    am = blockAllReduceMax(am);
    float scale = 127.0f / fmaxf(am, 1e-5f);
    char4 c;
    c.x = (char)max(-128, min(127, (int)rintf(nv.x * scale)));
    c.y = (char)max(-128, min(127, (int)rintf(nv.y * scale)));
    c.z = (char)max(-128, min(127, (int)rintf(nv.z * scale)));
    c.w = (char)max(-128, min(127, (int)rintf(nv.w * scale)));
    ((char4*)q)[base] = c;
    if (tid == 0) dq[t] = 1.0f / scale;
}
__global__ void k_quant_x(const float* __restrict__ x, const float* __restrict__ gain) {
    rowquant_body(x, gain, g_xq, g_xdq);
}
__global__ void k_quant_y(const float* __restrict__ gain) {
    rowquant_body(g_y, gain, g_yq, g_ydq);
}

// ---------------- tensor-core GEMMs ----------------
// Shared row stride: 64 data bytes + 16 pad = 80 B = 20 ints (conflict-free:
// row*20 mod 32 over 8 rows = {0,20,8,28,16,4,24,12}, a full distinct set).
#define ASTR 20
#define BUFI 2560            // ints per tile buffer (128 rows * 20)

// GEMM1: h = xq @ w1q^T with w1q[4096][768]; up = cols n, gate = cols HID+n.
// Block: 128 m x 64 paired cols (64 up + 64 gate = 128 outputs). 4 warps 2x2.
// Warp: 64 m x (32 up + 32 gate). Epilogue: y = silu(gate*s)*(up*s).
__global__ void __launch_bounds__(128, 1) k_gemm1() {
    __shared__ int sh[4 * BUFI];          // A0 B0 A1 B1 = 40 KB
    const int8_t* __restrict__ xq = g_xq;
    const int8_t* __restrict__ wq = g_w1q;
    int m0 = blockIdx.y << 7;
    int n0 = blockIdx.x << 6;
    int tid = threadIdx.x, lane = tid & 31, wid = tid >> 5;
    int wm = wid >> 1, wn = wid & 1;

    int acc[4][8][4];                      // [mt][nt: 0-3 up, 4-7 gate][c]
#pragma unroll
    for (int i = 0; i < 4; i++)
#pragma unroll
        for (int j = 0; j < 8; j++)
#pragma unroll
            for (int c = 0; c < 4; c++) acc[i][j][c] = 0;

    // tile loader: 512 A-chunks + 512 B-chunks of 16B; 128 threads
#define G1_LOAD(IT, BUF)                                                        \
    {                                                                           \
        int k0 = (IT) * 64;                                                     \
        int* Ab = sh + (BUF) * 2 * BUFI;                                        \
        int* Bb = Ab + BUFI;                                                    \
        _Pragma("unroll")                                                       \
        for (int c = tid; c < 512; c += 128) {                                  \
            int r = c >> 2, ck = c & 3;                                         \
            cp16(smem_u32(Ab + r * ASTR + ck * 4),                              \
                 xq + (size_t)(m0 + r) * DIM + k0 + ck * 16);                   \
            int nr = (r < 64) ? (n0 + r) : (HID + n0 + r - 64);                 \
            cp16(smem_u32(Bb + r * ASTR + ck * 4),                              \
                 wq + (size_t)nr * DIM + k0 + ck * 16);                         \
        }                                                                       \
    }

    G1_LOAD(0, 0); cp_commit();
#pragma unroll 1
    for (int it = 0; it < 12; it++) {
        if (it + 1 < 12) { G1_LOAD(it + 1, (it + 1) & 1); cp_commit(); cp_wait<1>(); }
        else cp_wait<0>();
        __syncthreads();
        int* Ab = sh + (it & 1) * 2 * BUFI;
        int* Bb = Ab + BUFI;
#pragma unroll
        for (int ks = 0; ks < 2; ks++) {
            int w = ks * 8 + (lane & 3);
            int a[4][4];
#pragma unroll
            for (int mt = 0; mt < 4; mt++) {
                int r = wm * 64 + mt * 16 + (lane >> 2);
                a[mt][0] = Ab[r * ASTR + w];
                a[mt][1] = Ab[(r + 8) * ASTR + w];
                a[mt][2] = Ab[r * ASTR + w + 4];
                a[mt][3] = Ab[(r + 8) * ASTR + w + 4];
            }
#pragma unroll
            for (int nt = 0; nt < 8; nt++) {
                int rn = ((nt < 4) ? (wn * 32 + nt * 8) : (64 + wn * 32 + (nt - 4) * 8))
                         + (lane >> 2);
                int b0 = Bb[rn * ASTR + w];
                int b1 = Bb[rn * ASTR + w + 4];
#pragma unroll
                for (int mt = 0; mt < 4; mt++)
                    mma_s8(acc[mt][nt], a[mt][0], a[mt][1], a[mt][2], a[mt][3], b0, b1);
            }
        }
        __syncthreads();
    }
#undef G1_LOAD

    // epilogue: swiglu + scale, write fp32 y
    float wdq = g_wdq[0];
#pragma unroll
    for (int mt = 0; mt < 4; mt++) {
        int r0 = m0 + wm * 64 + mt * 16 + (lane >> 2);
        float s0 = g_xdq[r0] * wdq;
        float s1 = g_xdq[r0 + 8] * wdq;
#pragma unroll
        for (int nt = 0; nt < 4; nt++) {
            int c = n0 + wn * 32 + nt * 8 + 2 * (lane & 3);
            int* u = acc[mt][nt];
            int* g = acc[mt][nt + 4];
            {
                float up0 = (float)u[0] * s0, gt0 = (float)g[0] * s0;
                float up1 = (float)u[1] * s0, gt1 = (float)g[1] * s0;
                float2 o;
                o.x = gt0 / (1.0f + expf(-gt0)) * up0;
                o.y = gt1 / (1.0f + expf(-gt1)) * up1;
                *(float2*)&g_y[(size_t)r0 * HID + c] = o;
            }
            {
                float up0 = (float)u[2] * s1, gt0 = (float)g[2] * s1;
                float up1 = (float)u[3] * s1, gt1 = (float)g[3] * s1;
                float2 o;
                o.x = gt0 / (1.0f + expf(-gt0)) * up0;
                o.y = gt1 / (1.0f + expf(-gt1)) * up1;
                *(float2*)&g_y[(size_t)(r0 + 8) * HID + c] = o;
            }
        }
    }
}

// GEMM2: out = yq @ w2q^T, w2q[768][2048]. Block 128x128, warps 2x2, warp 64x64.
__global__ void __launch_bounds__(128, 1) k_gemm2(float* __restrict__ out) {
    __shared__ int sh[4 * BUFI];
    const int8_t* __restrict__ yq = g_yq;
    const int8_t* __restrict__ wq = g_w2q;
    int m0 = blockIdx.y << 7;
    int n0 = blockIdx.x << 7;
    int tid = threadIdx.x, lane = tid & 31, wid = tid >> 5;
    int wm = wid >> 1, wn = wid & 1;

    int acc[4][8][4];
#pragma unroll
    for (int i = 0; i < 4; i++)
#pragma unroll
        for (int j = 0; j < 8; j++)
#pragma unroll
            for (int c = 0; c < 4; c++) acc[i][j][c] = 0;

#define G2_LOAD(IT, BUF)                                                        \
    {                                                                           \
        int k0 = (IT) * 64;                                                     \
        int* Ab = sh + (BUF) * 2 * BUFI;                                        \
        int* Bb = Ab + BUFI;                                                    \
        _Pragma("unroll")                                                       \
        for (int c = tid; c < 512; c += 128) {                                  \
            int r = c >> 2, ck = c & 3;                                         \
            cp16(smem_u32(Ab + r * ASTR + ck * 4),                              \
                 yq + (size_t)(m0 + r) * HID + k0 + ck * 16);                   \
            cp16(smem_u32(Bb + r * ASTR + ck * 4),                              \
                 wq + (size_t)(n0 + r) * HID + k0 + ck * 16);                   \
        }                                                                       \
    }

    G2_LOAD(0, 0); cp_commit();
#pragma unroll 1
    for (int it = 0; it < 32; it++) {
        if (it + 1 < 32) { G2_LOAD(it + 1, (it + 1) & 1); cp_commit(); cp_wait<1>(); }
        else cp_wait<0>();
        __syncthreads();
        int* Ab = sh + (it & 1) * 2 * BUFI;
        int* Bb = Ab + BUFI;
#pragma unroll
        for (int ks = 0; ks < 2; ks++) {
            int w = ks * 8 + (lane & 3);
            int a[4][4];
#pragma unroll
            for (int mt = 0; mt < 4; mt++) {
                int r = wm * 64 + mt * 16 + (lane >> 2);
                a[mt][0] = Ab[r * ASTR + w];
                a[mt][1] = Ab[(r + 8) * ASTR + w];
                a[mt][2] = Ab[r * ASTR + w + 4];
                a[mt][3] = Ab[(r + 8) * ASTR + w + 4];
            }
#pragma unroll
            for (int nt = 0; nt < 8; nt++) {
                int rn = wn * 64 + nt * 8 + (lane >> 2);
                int b0 = Bb[rn * ASTR + w];
                int b1 = Bb[rn * ASTR + w + 4];
#pragma unroll
                for (int mt = 0; mt < 4; mt++)
                    mma_s8(acc[mt][nt], a[mt][0], a[mt][1], a[mt][2], a[mt][3], b0, b1);
            }
        }
        __syncthreads();
    }
#undef G2_LOAD

    float wdq = g_wdq[1];
#pragma unroll
    for (int mt = 0; mt < 4; mt++) {
        int r0 = m0 + wm * 64 + mt * 16 + (lane >> 2);
        float s0 = g_ydq[r0] * wdq;
        float s1 = g_ydq[r0 + 8] * wdq;
#pragma unroll
        for (int nt = 0; nt < 8; nt++) {
            int c = n0 + wn * 64 + nt * 8 + 2 * (lane & 3);
            int* q = acc[mt][nt];
            float2 o0 = make_float2((float)q[0] * s0, (float)q[1] * s0);
            float2 o1 = make_float2((float)q[2] * s1, (float)q[3] * s1);
            *(float2*)&out[(size_t)r0 * DIM + c] = o0;
            *(float2*)&out[(size_t)(r0 + 8) * DIM + c] = o1;
        }
    }
}

// ---------------- eager init: absorb first-launch driver pool growth ----------------
namespace {
struct EagerInit {
    EagerInit() {
        cudaFree(0);
        void* py = nullptr; void* pdq = nullptr;
        cudaGetSymbolAddress(&py, g_y);
        cudaGetSymbolAddress(&pdq, g_xdq);
        const float* fy = (const float*)py;
        k_init<<<1, 1>>>();
        k_abssum<<<2, 256>>>(fy, 1024, 0);
        k_wquant<<<1, 256>>>(fy, 256, 0, 1.0);
        k_quant_x<<<1, DIM / 4>>>(fy, (const float*)pdq);
        k_quant_y<<<1, HID / 4>>>((const float*)pdq);
        k_gemm1<<<dim3(1, 1), 128>>>();
        k_gemm2<<<dim3(1, 1), 128>>>((float*)py);
        cudaDeviceSynchronize();
        cudaGetLastError();
    }
};
EagerInit eager_init_;
}  // namespace

// ---------------- launch ----------------
extern "C" void kernel_launch(void* const* d_in, const int* in_sizes, int n_in,
                              void* d_out, int out_size) {
    const float* x = nullptr, *w_in = nullptr, *gin = nullptr,
               *w_out = nullptr, *gout = nullptr;
    for (int i = 0; i < n_in; i++) {
        long long s = in_sizes[i];
        if (s == 25165824LL || s == 100663296LL)      x     = (const float*)d_in[i];
        else if (s == 3145728LL || s == 12582912LL)   w_in  = (const float*)d_in[i];
        else if (s == 1572864LL || s == 6291456LL)    w_out = (const float*)d_in[i];
        else if (s == 768LL     || s == 3072LL)       gin   = (const float*)d_in[i];
        else if (s == 2048LL    || s == 8192LL)       gout  = (const float*)d_in[i];
    }
    if (!x || !w_in || !gin || !w_out || !gout) {
        int idx[16];
        int m = n_in < 16 ? n_in : 16;
        for (int i = 0; i < m; i++) idx[i] = i;
        for (int a = 0; a < m; a++)
            for (int b = a + 1; b < m; b++)
                if ((long long)in_sizes[idx[b]] < (long long)in_sizes[idx[a]]) {
                    int t = idx[a]; idx[a] = idx[b]; idx[b] = t;
                }
        gin   = (const float*)d_in[idx[0]];
        gout  = (const float*)d_in[idx[1]];
        w_out = (const float*)d_in[idx[2]];
        w_in  = (const float*)d_in[idx[3]];
        x     = (const float*)d_in[idx[4]];
    }
    float* out = (float*)d_out;

    k_init<<<1, 1>>>();
    k_abssum<<<512, 256>>>(w_in,  N1 * DIM, 0);
    k_abssum<<<512, 256>>>(w_out, DIM * HID, 1);

    k_wquant<<<(N1 * DIM / 4 + 255) / 256, 256>>>(w_in,  N1 * DIM / 4, 0,
                                                  1.0 / (double)(N1 * DIM));
    k_wquant<<<(DIM * HID / 4 + 255) / 256, 256>>>(w_out, DIM * HID / 4, 1,
                                                   1.0 / (double)(DIM * HID));

    k_quant_x<<<TKN, DIM / 4>>>(x, gin);

    k_gemm1<<<dim3(HID / 64, TKN / 128), 128>>>();

    k_quant_y<<<TKN, HID / 4>>>(gout);

    k_gemm2<<<dim3(DIM / 128, TKN / 128), 128>>>(out);
}

// round 10
// speedup vs baseline: 3.4231x; 1.0049x over previous
#include <cuda_runtime.h>
#include <cuda_bf16.h>
#include <stdint.h>
#include <math.h>

// Problem dims (fixed)
#define TKN 32768        // B*S
#define DIM 768
#define HID 2048
#define N1  4096         // 2H

// ---------------- scratch ----------------
__device__ __align__(256) double g_acc[2];
__device__ __align__(256) float  g_wdq[2];
__device__ __align__(256) int8_t g_xq[(size_t)TKN * DIM];
__device__ __align__(256) float  g_xdq[TKN];
__device__ __align__(256) int8_t g_w1q[(size_t)N1 * DIM];
__device__ __align__(256) int8_t g_w2q[(size_t)DIM * HID];
__device__ __align__(256) float  g_y[(size_t)TKN * HID];   // fp32 (fp16 broke accuracy in R9)
__device__ __align__(256) int8_t g_yq[(size_t)TKN * HID];
__device__ __align__(256) float  g_ydq[TKN];

// ---------------- helpers ----------------
__device__ __forceinline__ uint32_t smem_u32(const void* p) {
    return (uint32_t)__cvta_generic_to_shared(p);
}
__device__ __forceinline__ void cp16(uint32_t s, const void* g) {
    asm volatile("cp.async.cg.shared.global [%0], [%1], 16;" :: "r"(s), "l"(g));
}
__device__ __forceinline__ void cp_commit() { asm volatile("cp.async.commit_group;"); }
template <int N> __device__ __forceinline__ void cp_wait() {
    asm volatile("cp.async.wait_group %0;" :: "n"(N));
}
__device__ __forceinline__ void mma_s8(int* c, int a0, int a1, int a2, int a3,
                                       int b0, int b1) {
    asm volatile(
        "mma.sync.aligned.m16n8k32.row.col.s32.s8.s8.s32 "
        "{%0,%1,%2,%3}, {%4,%5,%6,%7}, {%8,%9}, {%0,%1,%2,%3};"
        : "+r"(c[0]), "+r"(c[1]), "+r"(c[2]), "+r"(c[3])
        : "r"(a0), "r"(a1), "r"(a2), "r"(a3), "r"(b0), "r"(b1));
}

// ---------------- reductions ----------------
__device__ __forceinline__ float blockAllReduceSum(float v) {
    __shared__ float sm[17];
    int lane = threadIdx.x & 31, wid = threadIdx.x >> 5;
#pragma unroll
    for (int o = 16; o; o >>= 1) v += __shfl_down_sync(0xffffffffu, v, o);
    if (lane == 0) sm[wid] = v;
    __syncthreads();
    if (wid == 0) {
        float t = (lane < (int)(blockDim.x >> 5)) ? sm[lane] : 0.0f;
#pragma unroll
        for (int o = 16; o; o >>= 1) t += __shfl_down_sync(0xffffffffu, t, o);
        if (lane == 0) sm[16] = t;
    }
    __syncthreads();
    float r = sm[16];
    __syncthreads();
    return r;
}
__device__ __forceinline__ float blockAllReduceMax(float v) {
    __shared__ float sm[17];
    int lane = threadIdx.x & 31, wid = threadIdx.x >> 5;
#pragma unroll
    for (int o = 16; o; o >>= 1) v = fmaxf(v, __shfl_down_sync(0xffffffffu, v, o));
    if (lane == 0) sm[wid] = v;
    __syncthreads();
    if (wid == 0) {
        float t = (lane < (int)(blockDim.x >> 5)) ? sm[lane] : 0.0f;
#pragma unroll
        for (int o = 16; o; o >>= 1) t = fmaxf(t, __shfl_down_sync(0xffffffffu, t, o));
        if (lane == 0) sm[16] = t;
    }
    __syncthreads();
    float r = sm[16];
    __syncthreads();
    return r;
}

// ---------------- weight quantization ----------------
__global__ void k_init() { g_acc[0] = 0.0; g_acc[1] = 0.0; }

__global__ void k_abssum(const float* __restrict__ w, int n, int idx) {
    double s = 0.0;
    for (int i = blockIdx.x * blockDim.x + threadIdx.x; i < n; i += gridDim.x * blockDim.x)
        s += (double)fabsf(w[i]);
#pragma unroll
    for (int o = 16; o; o >>= 1) s += __shfl_down_sync(0xffffffffu, s, o);
    __shared__ double sm[8];
    int lane = threadIdx.x & 31, wid = threadIdx.x >> 5;
    if (lane == 0) sm[wid] = s;
    __syncthreads();
    if (wid == 0) {
        s = (lane < (int)(blockDim.x >> 5)) ? sm[lane] : 0.0;
#pragma unroll
        for (int o = 4; o; o >>= 1) s += __shfl_down_sync(0xffffffffu, s, o);
        if (lane == 0) atomicAdd(&g_acc[idx], s);
    }
}

// destination selected device-side (host must never pass __device__ symbols)
__global__ void k_wquant(const float* __restrict__ w, int n4, int idx, double inv_n) {
    int8_t* __restrict__ q = (idx == 0) ? g_w1q : g_w2q;
    float mean = (float)(g_acc[idx] * inv_n);
    float scale = 1.0f / fmaxf(mean, 1e-5f);
    int i = blockIdx.x * blockDim.x + threadIdx.x;
    if (i < n4) {
        float4 v = ((const float4*)w)[i];
        char4 c;
        c.x = (char)max(-1, min(1, (int)rintf(v.x * scale)));
        c.y = (char)max(-1, min(1, (int)rintf(v.y * scale)));
        c.z = (char)max(-1, min(1, (int)rintf(v.z * scale)));
        c.w = (char)max(-1, min(1, (int)rintf(v.w * scale)));
        ((char4*)q)[i] = c;
    }
    if (i == 0) g_wdq[idx] = 1.0f / scale;
}

// ---------------- fused rmsnorm + per-token int8 activation quant ----------------
__device__ __forceinline__ void rowquant_body(const float* __restrict__ in,
                                              const float* __restrict__ gain,
                                              int8_t* __restrict__ q,
                                              float* __restrict__ dq) {
    int t = blockIdx.x;
    int tid = threadIdx.x;
    int ld4 = blockDim.x;
    size_t base = (size_t)t * ld4 + tid;
    float4 v = ((const float4*)in)[base];
    float ss = v.x * v.x + v.y * v.y + v.z * v.z + v.w * v.w;
    ss = blockAllReduceSum(ss);
    float mn = ss / (float)(ld4 * 4) + 1e-6f;
    float rs = (float)(1.0 / sqrt((double)mn));
    float4 gv = ((const float4*)gain)[tid];
    float4 nv = make_float4((v.x * rs) * gv.x, (v.y * rs) * gv.y,
                            (v.z * rs) * gv.z, (v.w * rs) * gv.w);
    float am = fmaxf(fmaxf(fabsf(nv.x), fabsf(nv.y)), fmaxf(fabsf(nv.z), fabsf(nv.w)));
    am = blockAllReduceMax(am);
    float scale = 127.0f / fmaxf(am, 1e-5f);
    char4 c;
    c.x = (char)max(-128, min(127, (int)rintf(nv.x * scale)));
    c.y = (char)max(-128, min(127, (int)rintf(nv.y * scale)));
    c.z = (char)max(-128, min(127, (int)rintf(nv.z * scale)));
    c.w = (char)max(-128, min(127, (int)rintf(nv.w * scale)));
    ((char4*)q)[base] = c;
    if (tid == 0) dq[t] = 1.0f / scale;
}
__global__ void k_quant_x(const float* __restrict__ x, const float* __restrict__ gain) {
    rowquant_body(x, gain, g_xq, g_xdq);
}
__global__ void k_quant_y(const float* __restrict__ gain) {
    rowquant_body(g_y, gain, g_yq, g_ydq);
}

// ---------------- tensor-core GEMMs ----------------
// Shared row stride: 64 data bytes + 16 pad = 80 B = 20 ints (conflict-free).
#define ASTR 20
#define BUFI 2560            // ints per tile buffer (128 rows * 20)

// GEMM1: h = xq @ w1q^T; block 128m x (64 up + 64 gate); 4 warps 2x2.
__global__ void __launch_bounds__(128, 2) k_gemm1() {
    __shared__ int sh[4 * BUFI];          // 40 KB
    const int8_t* __restrict__ xq = g_xq;
    const int8_t* __restrict__ wq = g_w1q;
    int m0 = blockIdx.y << 7;
    int n0 = blockIdx.x << 6;
    int tid = threadIdx.x, lane = tid & 31, wid = tid >> 5;
    int wm = wid >> 1, wn = wid & 1;

    int acc[4][8][4];                      // [mt][nt: 0-3 up, 4-7 gate][c]
#pragma unroll
    for (int i = 0; i < 4; i++)
#pragma unroll
        for (int j = 0; j < 8; j++)
#pragma unroll
            for (int c = 0; c < 4; c++) acc[i][j][c] = 0;

#define G1_LOAD(IT, BUF)                                                        \
    {                                                                           \
        int k0 = (IT) * 64;                                                     \
        int* Ab = sh + (BUF) * 2 * BUFI;                                        \
        int* Bb = Ab + BUFI;                                                    \
        _Pragma("unroll")                                                       \
        for (int c = tid; c < 512; c += 128) {                                  \
            int r = c >> 2, ck = c & 3;                                         \
            cp16(smem_u32(Ab + r * ASTR + ck * 4),                              \
                 xq + (size_t)(m0 + r) * DIM + k0 + ck * 16);                   \
            int nr = (r < 64) ? (n0 + r) : (HID + n0 + r - 64);                 \
            cp16(smem_u32(Bb + r * ASTR + ck * 4),                              \
                 wq + (size_t)nr * DIM + k0 + ck * 16);                         \
        }                                                                       \
    }

    G1_LOAD(0, 0); cp_commit();
#pragma unroll 1
    for (int it = 0; it < 12; it++) {
        if (it + 1 < 12) { G1_LOAD(it + 1, (it + 1) & 1); cp_commit(); cp_wait<1>(); }
        else cp_wait<0>();
        __syncthreads();
        int* Ab = sh + (it & 1) * 2 * BUFI;
        int* Bb = Ab + BUFI;
#pragma unroll
        for (int ks = 0; ks < 2; ks++) {
            int w = ks * 8 + (lane & 3);
            int a[4][4];
#pragma unroll
            for (int mt = 0; mt < 4; mt++) {
                int r = wm * 64 + mt * 16 + (lane >> 2);
                a[mt][0] = Ab[r * ASTR + w];
                a[mt][1] = Ab[(r + 8) * ASTR + w];
                a[mt][2] = Ab[r * ASTR + w + 4];
                a[mt][3] = Ab[(r + 8) * ASTR + w + 4];
            }
#pragma unroll
            for (int nt = 0; nt < 8; nt++) {
                int rn = ((nt < 4) ? (wn * 32 + nt * 8) : (64 + wn * 32 + (nt - 4) * 8))
                         + (lane >> 2);
                int b0 = Bb[rn * ASTR + w];
                int b1 = Bb[rn * ASTR + w + 4];
#pragma unroll
                for (int mt = 0; mt < 4; mt++)
                    mma_s8(acc[mt][nt], a[mt][0], a[mt][1], a[mt][2], a[mt][3], b0, b1);
            }
        }
        __syncthreads();
    }
#undef G1_LOAD

    // epilogue: swiglu + scale, write fp32 y
    float wdq = g_wdq[0];
#pragma unroll
    for (int mt = 0; mt < 4; mt++) {
        int r0 = m0 + wm * 64 + mt * 16 + (lane >> 2);
        float s0 = g_xdq[r0] * wdq;
        float s1 = g_xdq[r0 + 8] * wdq;
#pragma unroll
        for (int nt = 0; nt < 4; nt++) {
            int c = n0 + wn * 32 + nt * 8 + 2 * (lane & 3);
            int* u = acc[mt][nt];
            int* g = acc[mt][nt + 4];
            {
                float up0 = (float)u[0] * s0, gt0 = (float)g[0] * s0;
                float up1 = (float)u[1] * s0, gt1 = (float)g[1] * s0;
                float2 o;
                o.x = gt0 / (1.0f + expf(-gt0)) * up0;
                o.y = gt1 / (1.0f + expf(-gt1)) * up1;
                *(float2*)&g_y[(size_t)r0 * HID + c] = o;
            }
            {
                float up0 = (float)u[2] * s1, gt0 = (float)g[2] * s1;
                float up1 = (float)u[3] * s1, gt1 = (float)g[3] * s1;
                float2 o;
                o.x = gt0 / (1.0f + expf(-gt0)) * up0;
                o.y = gt1 / (1.0f + expf(-gt1)) * up1;
                *(float2*)&g_y[(size_t)(r0 + 8) * HID + c] = o;
            }
        }
    }
}

// GEMM2: out = yq @ w2q^T. Block 128x128, warps 2x2, warp 64x64.
__global__ void __launch_bounds__(128, 2) k_gemm2(float* __restrict__ out) {
    __shared__ int sh[4 * BUFI];
    const int8_t* __restrict__ yq = g_yq;
    const int8_t* __restrict__ wq = g_w2q;
    int m0 = blockIdx.y << 7;
    int n0 = blockIdx.x << 7;
    int tid = threadIdx.x, lane = tid & 31, wid = tid >> 5;
    int wm = wid >> 1, wn = wid & 1;

    int acc[4][8][4];
#pragma unroll
    for (int i = 0; i < 4; i++)
#pragma unroll
        for (int j = 0; j < 8; j++)
#pragma unroll
            for (int c = 0; c < 4; c++) acc[i][j][c] = 0;

#define G2_LOAD(IT, BUF)                                                        \
    {                                                                           \
        int k0 = (IT) * 64;                                                     \
        int* Ab = sh + (BUF) * 2 * BUFI;                                        \
        int* Bb = Ab + BUFI;                                                    \
        _Pragma("unroll")                                                       \
        for (int c = tid; c < 512; c += 128) {                                  \
            int r = c >> 2, ck = c & 3;                                         \
            cp16(smem_u32(Ab + r * ASTR + ck * 4),                              \
                 yq + (size_t)(m0 + r) * HID + k0 + ck * 16);                   \
            cp16(smem_u32(Bb + r * ASTR + ck * 4),                              \
                 wq + (size_t)(n0 + r) * HID + k0 + ck * 16);                   \
        }                                                                       \
    }

    G2_LOAD(0, 0); cp_commit();
#pragma unroll 1
    for (int it = 0; it < 32; it++) {
        if (it + 1 < 32) { G2_LOAD(it + 1, (it + 1) & 1); cp_commit(); cp_wait<1>(); }
        else cp_wait<0>();
        __syncthreads();
        int* Ab = sh + (it & 1) * 2 * BUFI;
        int* Bb = Ab + BUFI;
#pragma unroll
        for (int ks = 0; ks < 2; ks++) {
            int w = ks * 8 + (lane & 3);
            int a[4][4];
#pragma unroll
            for (int mt = 0; mt < 4; mt++) {
                int r = wm * 64 + mt * 16 + (lane >> 2);
                a[mt][0] = Ab[r * ASTR + w];
                a[mt][1] = Ab[(r + 8) * ASTR + w];
                a[mt][2] = Ab[r * ASTR + w + 4];
                a[mt][3] = Ab[(r + 8) * ASTR + w + 4];
            }
#pragma unroll
            for (int nt = 0; nt < 8; nt++) {
                int rn = wn * 64 + nt * 8 + (lane >> 2);
                int b0 = Bb[rn * ASTR + w];
                int b1 = Bb[rn * ASTR + w + 4];
#pragma unroll
                for (int mt = 0; mt < 4; mt++)
                    mma_s8(acc[mt][nt], a[mt][0], a[mt][1], a[mt][2], a[mt][3], b0, b1);
            }
        }
        __syncthreads();
    }
#undef G2_LOAD

    float wdq = g_wdq[1];
#pragma unroll
    for (int mt = 0; mt < 4; mt++) {
        int r0 = m0 + wm * 64 + mt * 16 + (lane >> 2);
        float s0 = g_ydq[r0] * wdq;
        float s1 = g_ydq[r0 + 8] * wdq;
#pragma unroll
        for (int nt = 0; nt < 8; nt++) {
            int c = n0 + wn * 64 + nt * 8 + 2 * (lane & 3);
            int* q = acc[mt][nt];
            float2 o0 = make_float2((float)q[0] * s0, (float)q[1] * s0);
            float2 o1 = make_float2((float)q[2] * s1, (float)q[3] * s1);
            *(float2*)&out[(size_t)r0 * DIM + c] = o0;
            *(float2*)&out[(size_t)(r0 + 8) * DIM + c] = o1;
        }
    }
}

// ---------------- eager init: absorb first-launch driver pool growth ----------------
namespace {
struct EagerInit {
    EagerInit() {
        cudaFree(0);
        void* py = nullptr; void* pdq = nullptr;
        cudaGetSymbolAddress(&py, g_y);
        cudaGetSymbolAddress(&pdq, g_xdq);
        const float* fy = (const float*)py;
        k_init<<<1, 1>>>();
        k_abssum<<<2, 256>>>(fy, 1024, 0);
        k_wquant<<<1, 256>>>(fy, 256, 0, 1.0);
        k_quant_x<<<1, DIM / 4>>>(fy, (const float*)pdq);
        k_quant_y<<<1, HID / 4>>>((const float*)pdq);
        k_gemm1<<<dim3(1, 1), 128>>>();
        k_gemm2<<<dim3(1, 1), 128>>>((float*)py);
        cudaDeviceSynchronize();
        cudaGetLastError();
    }
};
EagerInit eager_init_;
}  // namespace

// ---------------- launch ----------------
extern "C" void kernel_launch(void* const* d_in, const int* in_sizes, int n_in,
                              void* d_out, int out_size) {
    const float* x = nullptr, *w_in = nullptr, *gin = nullptr,
               *w_out = nullptr, *gout = nullptr;
    for (int i = 0; i < n_in; i++) {
        long long s = in_sizes[i];
        if (s == 25165824LL || s == 100663296LL)      x     = (const float*)d_in[i];
        else if (s == 3145728LL || s == 12582912LL)   w_in  = (const float*)d_in[i];
        else if (s == 1572864LL || s == 6291456LL)    w_out = (const float*)d_in[i];
        else if (s == 768LL     || s == 3072LL)       gin   = (const float*)d_in[i];
        else if (s == 2048LL    || s == 8192LL)       gout  = (const float*)d_in[i];
    }
    if (!x || !w_in || !gin || !w_out || !gout) {
        int idx[16];
        int m = n_in < 16 ? n_in : 16;
        for (int i = 0; i < m; i++) idx[i] = i;
        for (int a = 0; a < m; a++)
            for (int b = a + 1; b < m; b++)
                if ((long long)in_sizes[idx[b]] < (long long)in_sizes[idx[a]]) {
                    int t = idx[a]; idx[a] = idx[b]; idx[b] = t;
                }
        gin   = (const float*)d_in[idx[0]];
        gout  = (const float*)d_in[idx[1]];
        w_out = (const float*)d_in[idx[2]];
        w_in  = (const float*)d_in[idx[3]];
        x     = (const float*)d_in[idx[4]];
    }
    float* out = (float*)d_out;

    k_init<<<1, 1>>>();
    k_abssum<<<512, 256>>>(w_in,  N1 * DIM, 0);
    k_abssum<<<512, 256>>>(w_out, DIM * HID, 1);

    k_wquant<<<(N1 * DIM / 4 + 255) / 256, 256>>>(w_in,  N1 * DIM / 4, 0,
                                                  1.0 / (double)(N1 * DIM));
    k_wquant<<<(DIM * HID / 4 + 255) / 256, 256>>>(w_out, DIM * HID / 4, 1,
                                                   1.0 / (double)(DIM * HID));

    k_quant_x<<<TKN, DIM / 4>>>(x, gin);

    k_gemm1<<<dim3(HID / 64, TKN / 128), 128>>>();

    k_quant_y<<<TKN, HID / 4>>>(gout);

    k_gemm2<<<dim3(DIM / 128, TKN / 128), 128>>>(out);
}